// round 15
// baseline (speedup 1.0000x reference)
#include <cuda_runtime.h>
#include <cstdint>

#define B_ 8
#define C_ 3
#define T_ 32
#define H_ 256
#define W_ 256
#define TPB 64
#define TILE_ROWS 16
#define CH_FLOATS (TILE_ROWS * W_)            // 4096 floats = 16 KB
#define TILE_BYTES_CH (CH_FLOATS * 4)         // 16384
#define TILE_BYTES (3 * TILE_BYTES_CH)        // 49152
#define SMEM_DYN (TILE_BYTES + 128)
#define BLOCKS_PER_FRAME 1024
#define CTAS_PER_FRAME 16
#define GRID (B_ * T_ * CTAS_PER_FRAME)       // 4096

// 2*cos(k*pi/16)
#define A1 1.96157056080646f
#define A2 1.84775906502257f
#define A3 1.66293922460509f
#define A4 1.41421356237310f
#define A5 1.11114046603920f
#define A6 0.76536686473018f
#define A7 0.39018064403226f

// Unnormalized DCT-II, 8 points, even/odd butterfly.
__device__ __forceinline__ void dct8(const float i0, const float i1, const float i2,
                                     const float i3, const float i4, const float i5,
                                     const float i6, const float i7, float o[8]) {
    float s0 = i0 + i7, s1 = i1 + i6, s2 = i2 + i5, s3 = i3 + i4;
    float d0 = i0 - i7, d1 = i1 - i6, d2 = i2 - i5, d3 = i3 - i4;
    o[0] = 2.0f * ((s0 + s3) + (s1 + s2));
    o[4] = A4 * ((s0 + s3) - (s1 + s2));
    o[2] = A2 * s0 + A6 * s1 - A6 * s2 - A2 * s3;
    o[6] = A6 * s0 - A2 * s1 + A2 * s2 - A6 * s3;
    o[1] = A1 * d0 + A3 * d1 + A5 * d2 + A7 * d3;
    o[3] = A3 * d0 - A7 * d1 - A1 * d2 - A5 * d3;
    o[5] = A5 * d0 - A1 * d1 + A7 * d2 + A3 * d3;
    o[7] = A7 * d0 - A5 * d1 + A3 * d2 - A1 * d3;
}

__device__ __forceinline__ uint32_t smem_u32(const void* p) {
    uint32_t a;
    asm("{ .reg .u64 t; cvta.to.shared.u64 t, %1; cvt.u32.u64 %0, t; }"
        : "=r"(a) : "l"(p));
    return a;
}

__global__ __launch_bounds__(TPB)
void dct8x8_kernel(const float* __restrict__ x, float* __restrict__ out) {
    extern __shared__ __align__(128) unsigned char smem_raw[];
    float* sin_ = (float*)smem_raw;                 // 3 x 16 x 256 floats
    const uint32_t sbase = smem_u32(smem_raw);
    const uint32_t mbar  = sbase + TILE_BYTES;      // 8B barrier after tile

    const int tid  = threadIdx.x;
    const int lane = tid & 31;
    const int warp = tid >> 5;
    const int band  = blockIdx.x & (CTAS_PER_FRAME - 1);   // 16-row band
    const int frame = blockIdx.x / CTAS_PER_FRAME;         // b*T + t
    const int b = frame >> 5;
    const int t = frame & 31;

    const long long chan_stride = (long long)T_ * H_ * W_;
    const float* src = x
        + (long long)b * C_ * chan_stride
        + (long long)t * H_ * W_
        + (long long)band * (TILE_ROWS * W_);

    // ---- bulk-async load: 3 contiguous 16KB channel chunks -> smem ----
    if (tid == 0) {
        asm volatile("mbarrier.init.shared.b64 [%0], 1;" :: "r"(mbar) : "memory");
    }
    __syncthreads();
    if (tid == 0) {
        asm volatile("mbarrier.arrive.expect_tx.shared.b64 _, [%0], %1;"
                     :: "r"(mbar), "r"((uint32_t)TILE_BYTES) : "memory");
        #pragma unroll
        for (int c = 0; c < 3; ++c) {
            asm volatile(
                "cp.async.bulk.shared::cluster.global.mbarrier::complete_tx::bytes "
                "[%0], [%1], %2, [%3];"
                :: "r"(sbase + c * TILE_BYTES_CH),
                   "l"(src + (long long)c * chan_stride),
                   "r"((uint32_t)TILE_BYTES_CH), "r"(mbar)
                : "memory");
        }
    }
    // all threads wait, phase parity 0 (barrier freshly init'd each launch)
    asm volatile(
        "{\n\t.reg .pred P;\n\t"
        "WAIT_%=:\n\t"
        "mbarrier.try_wait.parity.acquire.cta.shared::cta.b64 P, [%0], 0, 0x989680;\n\t"
        "@!P bra WAIT_%=;\n\t}"
        :: "r"(mbar) : "memory");

    // ---- compute: gray reduce + 2D DCT, one 8x8 block per thread ----
    const int hbi = tid >> 5;       // 0..1  block-row within band
    const int wbi = tid & 31;       // block-col
    const float w0 = 0.2989f, w1 = 0.587f, w2 = 0.114f;

    float Y[8][8];
    #pragma unroll
    for (int r = 0; r < 8; ++r) {
        const float* rp = sin_ + (hbi * 8 + r) * W_ + wbi * 8;
        float4 a0 = *(const float4*)(rp);
        float4 a1 = *(const float4*)(rp + 4);
        float4 g0 = *(const float4*)(rp + CH_FLOATS);
        float4 g1 = *(const float4*)(rp + CH_FLOATS + 4);
        float4 c0 = *(const float4*)(rp + 2 * CH_FLOATS);
        float4 c1 = *(const float4*)(rp + 2 * CH_FLOATS + 4);
        float p0 = w0 * a0.x + w1 * g0.x + w2 * c0.x;
        float p1 = w0 * a0.y + w1 * g0.y + w2 * c0.y;
        float p2 = w0 * a0.z + w1 * g0.z + w2 * c0.z;
        float p3 = w0 * a0.w + w1 * g0.w + w2 * c0.w;
        float p4 = w0 * a1.x + w1 * g1.x + w2 * c1.x;
        float p5 = w0 * a1.y + w1 * g1.y + w2 * c1.y;
        float p6 = w0 * a1.z + w1 * g1.z + w2 * c1.z;
        float p7 = w0 * a1.w + w1 * g1.w + w2 * c1.w;
        dct8(p0, p1, p2, p3, p4, p5, p6, p7, Y[r]);
    }

    float Z[8][8];
    #pragma unroll
    for (int l = 0; l < 8; ++l) {
        float col[8];
        dct8(Y[0][l], Y[1][l], Y[2][l], Y[3][l],
             Y[4][l], Y[5][l], Y[6][l], Y[7][l], col);
        #pragma unroll
        for (int k = 0; k < 8; ++k) Z[k][l] = col[k];
    }

    // ---- staged coalesced store (reuse input smem as stage buffer) ----
    __syncthreads();   // all input reads complete before overwrite

    float4* stage = (float4*)smem_raw;   // 64 threads * 256B = 16 KB
    const float4* zsrc = (const float4*)&Z[0][0];
    #pragma unroll
    for (int i = 0; i < 16; ++i) {
        stage[tid * 16 + (i ^ (tid & 15))] = zsrc[i];
    }
    __syncwarp();

    float4* out4 = (float4*)out
        + (long long)frame * (BLOCKS_PER_FRAME * 16)
        + (long long)band * (TPB * 16);
    #pragma unroll
    for (int c = 0; c < 16; ++c) {
        int m  = warp * 512 + c * 32 + lane;   // linear granule within CTA
        int tp = m >> 4;
        int j  = m & 15;
        float4 v = stage[tp * 16 + (j ^ (tp & 15))];
        __stcs(&out4[m], v);
    }
}

extern "C" void kernel_launch(void* const* d_in, const int* in_sizes, int n_in,
                              void* d_out, int out_size) {
    const float* x = (const float*)d_in[0];
    float* out = (float*)d_out;
    cudaFuncSetAttribute(dct8x8_kernel,
                         cudaFuncAttributeMaxDynamicSharedMemorySize, SMEM_DYN);
    dct8x8_kernel<<<GRID, TPB, SMEM_DYN>>>(x, out);
}